// round 13
// baseline (speedup 1.0000x reference)
#include <cuda_runtime.h>
#include <cuda_fp16.h>
#include <cstdint>

#define CD 768
#define ND 4096
#define BB 8

using fp16 = __half;

// ---------------------------------------------------------------------------
// Device scratch (module-load allocated; no runtime allocs)
// ---------------------------------------------------------------------------
__device__ fp16 g_x1n_hi[(size_t)BB * ND * CD];  // x1 natural [b][n][c]
__device__ fp16 g_x1n_lo[(size_t)BB * ND * CD];
__device__ fp16 g_x2n_hi[(size_t)BB * ND * CD];  // x2 natural [b][n][c]
__device__ fp16 g_x2n_lo[(size_t)BB * ND * CD];
__device__ float g_attn[(size_t)BB * CD * CD];   // fp32 logits
__device__ fp16 g_at_hi[(size_t)BB * CD * CD];   // softmaxed attn (fp16)

__device__ __constant__ float kScale = 0.10206207261596577f;  // (768/8)^-0.5

// ---------------------------------------------------------------------------
// PTX helpers
// ---------------------------------------------------------------------------
__device__ __forceinline__ uint32_t smem_u32(const void* p) {
    uint32_t a;
    asm("{ .reg .u64 t; cvta.to.shared.u64 t, %1; cvt.u32.u64 %0, t; }" : "=r"(a) : "l"(p));
    return a;
}

__device__ __forceinline__ void cp_async16(uint32_t saddr, const void* gaddr) {
    asm volatile("cp.async.cg.shared.global [%0], [%1], 16;" :: "r"(saddr), "l"(gaddr));
}
#define CP_COMMIT() asm volatile("cp.async.commit_group;" ::: "memory")
#define CP_WAIT(n)  asm volatile("cp.async.wait_group %0;" :: "n"(n) : "memory")

__device__ __forceinline__ void ldsm4(uint32_t& r0, uint32_t& r1, uint32_t& r2,
                                      uint32_t& r3, uint32_t addr) {
    asm volatile("ldmatrix.sync.aligned.m8n8.x4.shared.b16 {%0,%1,%2,%3}, [%4];"
                 : "=r"(r0), "=r"(r1), "=r"(r2), "=r"(r3) : "r"(addr));
}
__device__ __forceinline__ void ldsm4t(uint32_t& r0, uint32_t& r1, uint32_t& r2,
                                       uint32_t& r3, uint32_t addr) {
    asm volatile("ldmatrix.sync.aligned.m8n8.x4.trans.shared.b16 {%0,%1,%2,%3}, [%4];"
                 : "=r"(r0), "=r"(r1), "=r"(r2), "=r"(r3) : "r"(addr));
}

__device__ __forceinline__ void mma_f16(float* c, const uint32_t* a, const uint32_t* b) {
    asm volatile(
        "mma.sync.aligned.m16n8k16.row.col.f32.f16.f16.f32 "
        "{%0,%1,%2,%3}, {%4,%5,%6,%7}, {%8,%9}, {%0,%1,%2,%3};"
        : "+f"(c[0]), "+f"(c[1]), "+f"(c[2]), "+f"(c[3])
        : "r"(a[0]), "r"(a[1]), "r"(a[2]), "r"(a[3]), "r"(b[0]), "r"(b[1]));
}

// ---------------------------------------------------------------------------
// Streaming fp16 split, both tensors in one launch, packed converts.
// ---------------------------------------------------------------------------
__global__ __launch_bounds__(256) void split_kernel(const float* __restrict__ x1,
                                                    const float* __restrict__ x2) {
    const int half = gridDim.x >> 1;
    const float* src;
    fp16 *dh, *dl;
    int blk = blockIdx.x;
    if (blk < half) {
        src = x1; dh = g_x1n_hi; dl = g_x1n_lo;
    } else {
        src = x2; dh = g_x2n_hi; dl = g_x2n_lo;
        blk -= half;
    }
    size_t i = ((size_t)blk * 256 + threadIdx.x) * 8;
    float4 v0 = *(const float4*)(src + i);
    float4 v1 = *(const float4*)(src + i + 4);

    __half2 h[4], l[4];
    h[0] = __float22half2_rn(make_float2(v0.x, v0.y));
    h[1] = __float22half2_rn(make_float2(v0.z, v0.w));
    h[2] = __float22half2_rn(make_float2(v1.x, v1.y));
    h[3] = __float22half2_rn(make_float2(v1.z, v1.w));
    float2 r0 = __half22float2(h[0]);
    float2 r1 = __half22float2(h[1]);
    float2 r2 = __half22float2(h[2]);
    float2 r3 = __half22float2(h[3]);
    l[0] = __float22half2_rn(make_float2(v0.x - r0.x, v0.y - r0.y));
    l[1] = __float22half2_rn(make_float2(v0.z - r1.x, v0.w - r1.y));
    l[2] = __float22half2_rn(make_float2(v1.x - r2.x, v1.y - r2.y));
    l[3] = __float22half2_rn(make_float2(v1.z - r3.x, v1.w - r3.y));

    *(uint4*)(dh + i) = *(uint4*)h;
    *(uint4*)(dl + i) = *(uint4*)l;
}

// ---------------------------------------------------------------------------
// Softmax over g_attn rows -> fp16 attn
// ---------------------------------------------------------------------------
__global__ __launch_bounds__(256) void softmax_kernel() {
    const size_t ro = (size_t)blockIdx.x * CD;
    float* p = g_attn + ro;
    const int tid = threadIdx.x;

    float v0 = p[tid], v1 = p[tid + 256], v2 = p[tid + 512];

    float m = fmaxf(fmaxf(v0, v1), v2);
#pragma unroll
    for (int o = 16; o > 0; o >>= 1) m = fmaxf(m, __shfl_xor_sync(0xffffffffu, m, o));

    __shared__ float sm[8], ss[8];
    if ((tid & 31) == 0) sm[tid >> 5] = m;
    __syncthreads();
    float bm = sm[0];
#pragma unroll
    for (int i = 1; i < 8; i++) bm = fmaxf(bm, sm[i]);

    float e0 = __expf(v0 - bm), e1 = __expf(v1 - bm), e2 = __expf(v2 - bm);
    float s = e0 + e1 + e2;
#pragma unroll
    for (int o = 16; o > 0; o >>= 1) s += __shfl_xor_sync(0xffffffffu, s, o);
    if ((tid & 31) == 0) ss[tid >> 5] = s;
    __syncthreads();
    float bs = 0.f;
#pragma unroll
    for (int i = 0; i < 8; i++) bs += ss[i];

    float inv = 1.0f / bs;
    g_at_hi[ro + tid]       = __float2half_rn(e0 * inv);
    g_at_hi[ro + tid + 256] = __float2half_rn(e1 * inv);
    g_at_hi[ro + tid + 512] = __float2half_rn(e2 * inv);
}

// ---------------------------------------------------------------------------
// GEMM1 (logits): attn[m][n] = scale * sum_k x1[k][m]*x2[k][n], k = seq dim.
// Natural [n][c] operands, ldmatrix.trans fragments, 3-term fp16 split.
// CTA 128x128, 256 threads, BK=32, 3-stage, one barrier per chunk.
// ---------------------------------------------------------------------------
static constexpr int ROW2 = 272;
static constexpr int TEN2 = 32 * ROW2;      // 8704
static constexpr int STG2 = 4 * TEN2;       // 34816
static constexpr int SM1 = 3 * STG2;        // 104448

__global__ __launch_bounds__(256) void gemm1_kernel() {
    extern __shared__ char smc[];
    const uint32_t smb = smem_u32(smc);
    const int tid = threadIdx.x;
    const int wid = tid >> 5, lane = tid & 31;
    const int wm = wid >> 2, wn = wid & 3;
    const int b = blockIdx.z;
    const int m0 = blockIdx.y * 128;
    const int n0 = blockIdx.x * 128;

    const fp16* pAh = g_x1n_hi + (size_t)b * ND * CD + m0;
    const fp16* pAl = g_x1n_lo + (size_t)b * ND * CD + m0;
    const fp16* pBh = g_x2n_hi + (size_t)b * ND * CD + n0;
    const fp16* pBl = g_x2n_lo + (size_t)b * ND * CD + n0;
    float* Cp = g_attn + (size_t)b * CD * CD;

    auto issue = [&](int c, int buf) {
        const int k0 = c * 32;
        const uint32_t sb = smb + buf * STG2;
#pragma unroll
        for (int h = 0; h < 2; h++) {
            const int idx = tid + h * 256;
            const int row = idx >> 4, seg = idx & 15;
            const uint32_t so = (uint32_t)row * ROW2 + seg * 16;
            const size_t go = (size_t)(k0 + row) * CD + seg * 8;
            cp_async16(sb + so, pAh + go);
            cp_async16(sb + TEN2 + so, pAl + go);
            cp_async16(sb + 2 * TEN2 + so, pBh + go);
            cp_async16(sb + 3 * TEN2 + so, pBl + go);
        }
        CP_COMMIT();
    };

    float acc[4][4][4] = {};
    constexpr int NC = ND / 32;  // 128

    issue(0, 0);
    issue(1, 1);

    const int a_kr = ((lane >> 4) << 3) + (lane & 7);
    const int a_mc = (lane >> 3) & 1;
    const int b_kr = (((lane >> 3) & 1) << 3) + (lane & 7);
    const int b_nc = lane >> 4;

    int buf = 0;
    for (int c = 0; c < NC; c++) {
        const bool more = (c + 2 < NC);
        if (more) { CP_WAIT(1); } else { CP_WAIT(0); }
        __syncthreads();

        const uint32_t sA = smb + buf * STG2;
        const uint32_t sB = sA + 2 * TEN2;

        uint32_t ah[4][4], al[4][4], bh[2][4], bl[2][4];

        auto load_frags = [&](int ks) {
            const uint32_t akro = (uint32_t)(ks * 16 + a_kr) * ROW2;
            const uint32_t bkro = (uint32_t)(ks * 16 + b_kr) * ROW2;
#pragma unroll
            for (int mt = 0; mt < 4; mt++) {
                uint32_t addr = sA + akro + (uint32_t)(wm * 128 + mt * 32 + a_mc * 16);
                ldsm4t(ah[mt][0], ah[mt][1], ah[mt][2], ah[mt][3], addr);
                ldsm4t(al[mt][0], al[mt][1], al[mt][2], al[mt][3], addr + TEN2);
            }
#pragma unroll
            for (int np = 0; np < 2; np++) {
                uint32_t addr = sB + bkro + (uint32_t)(wn * 64 + np * 32 + b_nc * 16);
                ldsm4t(bh[np][0], bh[np][1], bh[np][2], bh[np][3], addr);
                ldsm4t(bl[np][0], bl[np][1], bl[np][2], bl[np][3], addr + TEN2);
            }
        };
        auto mma_all = [&]() {
#pragma unroll
            for (int mt = 0; mt < 4; mt++)
#pragma unroll
                for (int nt = 0; nt < 4; nt++) {
                    const uint32_t* bph = &bh[nt >> 1][(nt & 1) * 2];
                    const uint32_t* bpl = &bl[nt >> 1][(nt & 1) * 2];
                    mma_f16(acc[mt][nt], ah[mt], bph);
                    mma_f16(acc[mt][nt], ah[mt], bpl);
                    mma_f16(acc[mt][nt], al[mt], bph);
                }
        };

        load_frags(0);
        if (more) {
            int nb = buf + 2; if (nb >= 3) nb -= 3;
            issue(c + 2, nb);
        }
        mma_all();
        load_frags(1);
        mma_all();

        buf++; if (buf == 3) buf = 0;
    }

    const int er = lane >> 2, ec = (lane & 3) * 2;
#pragma unroll
    for (int mt = 0; mt < 4; mt++) {
#pragma unroll
        for (int nt = 0; nt < 4; nt++) {
            float* a4 = acc[mt][nt];
            const int row = m0 + wm * 64 + mt * 16 + er;
            const int col = n0 + wn * 32 + nt * 8 + ec;
            *(float2*)(Cp + (size_t)row * CD + col) =
                make_float2(a4[0] * kScale, a4[1] * kScale);
            *(float2*)(Cp + (size_t)(row + 8) * CD + col) =
                make_float2(a4[2] * kScale, a4[3] * kScale);
        }
    }
}

// ---------------------------------------------------------------------------
// GEMM2 (out): out[m][n] = sum_k attn[m][k]*x2[n][k], k = channel (768).
// K-contiguous, non-trans ldmatrix, ONE-TERM fp16 x fp16.
// CTA tile 96x128 -> 2048 tiles = 6.92 waves of 296 (kills wave quantization).
// 8 warps (2m x 4n), warp tile 48x32 (mt=3). BK=32, 3-stage. 2 CTAs/SM.
// ---------------------------------------------------------------------------
static constexpr int ROWB = 80;
static constexpr int TA96 = 96 * ROWB;      // 7680  (A: 96 m-rows)
static constexpr int TB2 = 128 * ROWB;      // 10240 (B: 128 n-rows)
static constexpr int STG3 = TA96 + TB2;     // 17920
static constexpr int SM2 = 3 * STG3;        // 53760

__global__ __launch_bounds__(256) void gemm2_kernel(float* __restrict__ Cout) {
    extern __shared__ char smc[];
    const uint32_t smb = smem_u32(smc);
    const int tid = threadIdx.x;
    const int wid = tid >> 5, lane = tid & 31;
    const int wm = wid >> 2, wn = wid & 3;   // 2 x 4 warps
    const int b = blockIdx.z;
    const int m0 = blockIdx.y * 96;
    const int n0 = blockIdx.x * 128;

    const fp16* pAh = g_at_hi + (size_t)b * CD * CD + (size_t)m0 * CD;
    const fp16* pBh = g_x2n_hi + (size_t)b * ND * CD + (size_t)n0 * CD;
    float* Cp = Cout + (size_t)b * CD * ND;

    // loader: A = 384 16B-chunks, B = 512 -> 896 total, 4 rounds of 256 (last partial)
    auto issue = [&](int c, int buf) {
        const int k0 = c * 32;
        const uint32_t sb = smb + buf * STG3;
#pragma unroll
        for (int it = 0; it < 4; it++) {
            const int idx = tid + it * 256;
            if (idx < 384) {
                const int row = idx >> 2, seg = idx & 3;
                cp_async16(sb + (uint32_t)row * ROWB + seg * 16,
                           pAh + (size_t)row * CD + k0 + seg * 8);
            } else if (idx < 896) {
                const int j = idx - 384;
                const int row = j >> 2, seg = j & 3;
                cp_async16(sb + TA96 + (uint32_t)row * ROWB + seg * 16,
                           pBh + (size_t)row * CD + k0 + seg * 8);
            }
        }
        CP_COMMIT();
    };

    float acc[3][4][4] = {};
    constexpr int NC = CD / 32;  // 24

    issue(0, 0);
    issue(1, 1);

    const int a_r = lane & 15, a_h = lane >> 4;
    const int b_r = (lane & 7) + ((lane >> 4) << 3);
    const int b_h = (lane >> 3) & 1;

    int buf = 0;
    for (int c = 0; c < NC; c++) {
        const bool more = (c + 2 < NC);
        if (more) { CP_WAIT(1); } else { CP_WAIT(0); }
        __syncthreads();

        const uint32_t sA = smb + buf * STG3;
        const uint32_t sB = sA + TA96;

        uint32_t ah[3][4], bh[2][4];

        auto load_frags = [&](int ks) {
            const uint32_t kso = ks * 32;
#pragma unroll
            for (int mt = 0; mt < 3; mt++) {
                uint32_t addr = sA + (uint32_t)(wm * 48 + mt * 16 + a_r) * ROWB + kso + a_h * 16;
                ldsm4(ah[mt][0], ah[mt][1], ah[mt][2], ah[mt][3], addr);
            }
#pragma unroll
            for (int np = 0; np < 2; np++) {
                uint32_t addr = sB + (uint32_t)(wn * 32 + np * 16 + b_r) * ROWB + kso + b_h * 16;
                ldsm4(bh[np][0], bh[np][1], bh[np][2], bh[np][3], addr);
            }
        };
        auto mma_all = [&]() {
#pragma unroll
            for (int mt = 0; mt < 3; mt++)
#pragma unroll
                for (int nt = 0; nt < 4; nt++) {
                    const uint32_t* bph = &bh[nt >> 1][(nt & 1) * 2];
                    mma_f16(acc[mt][nt], ah[mt], bph);
                }
        };

        load_frags(0);
        if (more) {
            int nb = buf + 2; if (nb >= 3) nb -= 3;
            issue(c + 2, nb);
        }
        mma_all();
        load_frags(1);
        mma_all();

        buf++; if (buf == 3) buf = 0;
    }

    const int er = lane >> 2, ec = (lane & 3) * 2;
#pragma unroll
    for (int mt = 0; mt < 3; mt++) {
#pragma unroll
        for (int nt = 0; nt < 4; nt++) {
            float* a4 = acc[mt][nt];
            const int row = m0 + wm * 48 + mt * 16 + er;
            const int col = n0 + wn * 32 + nt * 8 + ec;
            *(float2*)(Cp + (size_t)row * ND + col) = make_float2(a4[0], a4[1]);
            *(float2*)(Cp + (size_t)(row + 8) * ND + col) = make_float2(a4[2], a4[3]);
        }
    }
}

// ---------------------------------------------------------------------------
extern "C" void kernel_launch(void* const* d_in, const int* in_sizes, int n_in,
                              void* d_out, int out_size) {
    const float* x1 = (const float*)d_in[0];
    const float* x2 = (const float*)d_in[1];
    float* out = (float*)d_out;

    cudaFuncSetAttribute(gemm1_kernel,
                         cudaFuncAttributeMaxDynamicSharedMemorySize, SM1);
    cudaFuncSetAttribute(gemm2_kernel,
                         cudaFuncAttributeMaxDynamicSharedMemorySize, SM2);

    const int half = (int)((size_t)BB * ND * CD / 2048);  // 8 floats/thread
    split_kernel<<<2 * half, 256>>>(x1, x2);

    dim3 g1(CD / 128, CD / 128, BB);  // 6 x 6 x 8 = 288 CTAs (one wave)
    gemm1_kernel<<<g1, 256, SM1>>>();

    softmax_kernel<<<BB * CD, 256>>>();

    dim3 g2(ND / 128, CD / 96, BB);   // 32 x 8 x 8 = 2048 CTAs (6.92 waves)
    gemm2_kernel<<<g2, 256, SM2>>>(out);
}

// round 14
// speedup vs baseline: 1.0552x; 1.0552x over previous
#include <cuda_runtime.h>
#include <cuda_fp16.h>
#include <cstdint>

#define CD 768
#define ND 4096
#define BB 8

using fp16 = __half;

// ---------------------------------------------------------------------------
// Device scratch (module-load allocated; no runtime allocs)
// ---------------------------------------------------------------------------
__device__ fp16 g_x1n_hi[(size_t)BB * ND * CD];  // x1 natural [b][n][c]
__device__ fp16 g_x1n_lo[(size_t)BB * ND * CD];
__device__ fp16 g_x2n_hi[(size_t)BB * ND * CD];  // x2 natural [b][n][c]
__device__ fp16 g_x2n_lo[(size_t)BB * ND * CD];
__device__ float g_attn[(size_t)BB * CD * CD];   // fp32 logits
__device__ fp16 g_at_hi[(size_t)BB * CD * CD];   // softmaxed attn (fp16)

__device__ __constant__ float kScale = 0.10206207261596577f;  // (768/8)^-0.5

// ---------------------------------------------------------------------------
// PTX helpers
// ---------------------------------------------------------------------------
__device__ __forceinline__ uint32_t smem_u32(const void* p) {
    uint32_t a;
    asm("{ .reg .u64 t; cvta.to.shared.u64 t, %1; cvt.u32.u64 %0, t; }" : "=r"(a) : "l"(p));
    return a;
}

__device__ __forceinline__ void cp_async16(uint32_t saddr, const void* gaddr) {
    asm volatile("cp.async.cg.shared.global [%0], [%1], 16;" :: "r"(saddr), "l"(gaddr));
}
#define CP_COMMIT() asm volatile("cp.async.commit_group;" ::: "memory")
#define CP_WAIT(n)  asm volatile("cp.async.wait_group %0;" :: "n"(n) : "memory")

__device__ __forceinline__ void ldsm4(uint32_t& r0, uint32_t& r1, uint32_t& r2,
                                      uint32_t& r3, uint32_t addr) {
    asm volatile("ldmatrix.sync.aligned.m8n8.x4.shared.b16 {%0,%1,%2,%3}, [%4];"
                 : "=r"(r0), "=r"(r1), "=r"(r2), "=r"(r3) : "r"(addr));
}
__device__ __forceinline__ void ldsm4t(uint32_t& r0, uint32_t& r1, uint32_t& r2,
                                       uint32_t& r3, uint32_t addr) {
    asm volatile("ldmatrix.sync.aligned.m8n8.x4.trans.shared.b16 {%0,%1,%2,%3}, [%4];"
                 : "=r"(r0), "=r"(r1), "=r"(r2), "=r"(r3) : "r"(addr));
}

__device__ __forceinline__ void mma_f16(float* c, const uint32_t* a, const uint32_t* b) {
    asm volatile(
        "mma.sync.aligned.m16n8k16.row.col.f32.f16.f16.f32 "
        "{%0,%1,%2,%3}, {%4,%5,%6,%7}, {%8,%9}, {%0,%1,%2,%3};"
        : "+f"(c[0]), "+f"(c[1]), "+f"(c[2]), "+f"(c[3])
        : "r"(a[0]), "r"(a[1]), "r"(a[2]), "r"(a[3]), "r"(b[0]), "r"(b[1]));
}

// ---------------------------------------------------------------------------
// Streaming fp16 split, both tensors in one launch, packed converts.
// ---------------------------------------------------------------------------
__global__ __launch_bounds__(256) void split_kernel(const float* __restrict__ x1,
                                                    const float* __restrict__ x2) {
    const int half = gridDim.x >> 1;
    const float* src;
    fp16 *dh, *dl;
    int blk = blockIdx.x;
    if (blk < half) {
        src = x1; dh = g_x1n_hi; dl = g_x1n_lo;
    } else {
        src = x2; dh = g_x2n_hi; dl = g_x2n_lo;
        blk -= half;
    }
    size_t i = ((size_t)blk * 256 + threadIdx.x) * 8;
    float4 v0 = *(const float4*)(src + i);
    float4 v1 = *(const float4*)(src + i + 4);

    __half2 h[4], l[4];
    h[0] = __float22half2_rn(make_float2(v0.x, v0.y));
    h[1] = __float22half2_rn(make_float2(v0.z, v0.w));
    h[2] = __float22half2_rn(make_float2(v1.x, v1.y));
    h[3] = __float22half2_rn(make_float2(v1.z, v1.w));
    float2 r0 = __half22float2(h[0]);
    float2 r1 = __half22float2(h[1]);
    float2 r2 = __half22float2(h[2]);
    float2 r3 = __half22float2(h[3]);
    l[0] = __float22half2_rn(make_float2(v0.x - r0.x, v0.y - r0.y));
    l[1] = __float22half2_rn(make_float2(v0.z - r1.x, v0.w - r1.y));
    l[2] = __float22half2_rn(make_float2(v1.x - r2.x, v1.y - r2.y));
    l[3] = __float22half2_rn(make_float2(v1.z - r3.x, v1.w - r3.y));

    *(uint4*)(dh + i) = *(uint4*)h;
    *(uint4*)(dl + i) = *(uint4*)l;
}

// ---------------------------------------------------------------------------
// Softmax over g_attn rows -> fp16 attn
// ---------------------------------------------------------------------------
__global__ __launch_bounds__(256) void softmax_kernel() {
    const size_t ro = (size_t)blockIdx.x * CD;
    float* p = g_attn + ro;
    const int tid = threadIdx.x;

    float v0 = p[tid], v1 = p[tid + 256], v2 = p[tid + 512];

    float m = fmaxf(fmaxf(v0, v1), v2);
#pragma unroll
    for (int o = 16; o > 0; o >>= 1) m = fmaxf(m, __shfl_xor_sync(0xffffffffu, m, o));

    __shared__ float sm[8], ss[8];
    if ((tid & 31) == 0) sm[tid >> 5] = m;
    __syncthreads();
    float bm = sm[0];
#pragma unroll
    for (int i = 1; i < 8; i++) bm = fmaxf(bm, sm[i]);

    float e0 = __expf(v0 - bm), e1 = __expf(v1 - bm), e2 = __expf(v2 - bm);
    float s = e0 + e1 + e2;
#pragma unroll
    for (int o = 16; o > 0; o >>= 1) s += __shfl_xor_sync(0xffffffffu, s, o);
    if ((tid & 31) == 0) ss[tid >> 5] = s;
    __syncthreads();
    float bs = 0.f;
#pragma unroll
    for (int i = 0; i < 8; i++) bs += ss[i];

    float inv = 1.0f / bs;
    g_at_hi[ro + tid]       = __float2half_rn(e0 * inv);
    g_at_hi[ro + tid + 256] = __float2half_rn(e1 * inv);
    g_at_hi[ro + tid + 512] = __float2half_rn(e2 * inv);
}

// ---------------------------------------------------------------------------
// GEMM1 (logits): attn[m][n] = scale * sum_k x1[k][m]*x2[k][n], k = seq dim.
// Natural [n][c] operands, ldmatrix.trans fragments, 3-term fp16 split.
// CTA 128x128, 256 threads, BK=32, 3-stage, one barrier per chunk.
// cp.async issue split into two half-bursts (after each ldsm batch).
// ---------------------------------------------------------------------------
static constexpr int ROW2 = 272;
static constexpr int TEN2 = 32 * ROW2;      // 8704
static constexpr int STG2 = 4 * TEN2;       // 34816
static constexpr int SM1 = 3 * STG2;        // 104448

__global__ __launch_bounds__(256) void gemm1_kernel() {
    extern __shared__ char smc[];
    const uint32_t smb = smem_u32(smc);
    const int tid = threadIdx.x;
    const int wid = tid >> 5, lane = tid & 31;
    const int wm = wid >> 2, wn = wid & 3;
    const int b = blockIdx.z;
    const int m0 = blockIdx.y * 128;
    const int n0 = blockIdx.x * 128;

    const fp16* pAh = g_x1n_hi + (size_t)b * ND * CD + m0;
    const fp16* pAl = g_x1n_lo + (size_t)b * ND * CD + m0;
    const fp16* pBh = g_x2n_hi + (size_t)b * ND * CD + n0;
    const fp16* pBl = g_x2n_lo + (size_t)b * ND * CD + n0;
    float* Cp = g_attn + (size_t)b * CD * CD;

    // one half-burst (h = 0 or 1); commit only after h = 1
    auto issue_half = [&](int c, int buf, int h) {
        const int k0 = c * 32;
        const uint32_t sb = smb + buf * STG2;
        const int idx = tid + h * 256;
        const int row = idx >> 4, seg = idx & 15;
        const uint32_t so = (uint32_t)row * ROW2 + seg * 16;
        const size_t go = (size_t)(k0 + row) * CD + seg * 8;
        cp_async16(sb + so, pAh + go);
        cp_async16(sb + TEN2 + so, pAl + go);
        cp_async16(sb + 2 * TEN2 + so, pBh + go);
        cp_async16(sb + 3 * TEN2 + so, pBl + go);
    };
    auto issue = [&](int c, int buf) {
        issue_half(c, buf, 0);
        issue_half(c, buf, 1);
        CP_COMMIT();
    };

    float acc[4][4][4] = {};
    constexpr int NC = ND / 32;  // 128

    issue(0, 0);
    issue(1, 1);

    const int a_kr = ((lane >> 4) << 3) + (lane & 7);
    const int a_mc = (lane >> 3) & 1;
    const int b_kr = (((lane >> 3) & 1) << 3) + (lane & 7);
    const int b_nc = lane >> 4;

    int buf = 0;
    for (int c = 0; c < NC; c++) {
        const bool more = (c + 2 < NC);
        if (more) { CP_WAIT(1); } else { CP_WAIT(0); }
        __syncthreads();

        const uint32_t sA = smb + buf * STG2;
        const uint32_t sB = sA + 2 * TEN2;
        int nb = buf + 2; if (nb >= 3) nb -= 3;

        uint32_t ah[4][4], al[4][4], bh[2][4], bl[2][4];

        auto load_frags = [&](int ks) {
            const uint32_t akro = (uint32_t)(ks * 16 + a_kr) * ROW2;
            const uint32_t bkro = (uint32_t)(ks * 16 + b_kr) * ROW2;
#pragma unroll
            for (int mt = 0; mt < 4; mt++) {
                uint32_t addr = sA + akro + (uint32_t)(wm * 128 + mt * 32 + a_mc * 16);
                ldsm4t(ah[mt][0], ah[mt][1], ah[mt][2], ah[mt][3], addr);
                ldsm4t(al[mt][0], al[mt][1], al[mt][2], al[mt][3], addr + TEN2);
            }
#pragma unroll
            for (int np = 0; np < 2; np++) {
                uint32_t addr = sB + bkro + (uint32_t)(wn * 64 + np * 32 + b_nc * 16);
                ldsm4t(bh[np][0], bh[np][1], bh[np][2], bh[np][3], addr);
                ldsm4t(bl[np][0], bl[np][1], bl[np][2], bl[np][3], addr + TEN2);
            }
        };
        auto mma_all = [&]() {
#pragma unroll
            for (int mt = 0; mt < 4; mt++)
#pragma unroll
                for (int nt = 0; nt < 4; nt++) {
                    const uint32_t* bph = &bh[nt >> 1][(nt & 1) * 2];
                    const uint32_t* bpl = &bl[nt >> 1][(nt & 1) * 2];
                    mma_f16(acc[mt][nt], ah[mt], bph);
                    mma_f16(acc[mt][nt], ah[mt], bpl);
                    mma_f16(acc[mt][nt], al[mt], bph);
                }
        };

        load_frags(0);
        if (more) issue_half(c + 2, nb, 0);
        mma_all();
        load_frags(1);
        if (more) { issue_half(c + 2, nb, 1); CP_COMMIT(); }
        mma_all();

        buf++; if (buf == 3) buf = 0;
    }

    const int er = lane >> 2, ec = (lane & 3) * 2;
#pragma unroll
    for (int mt = 0; mt < 4; mt++) {
#pragma unroll
        for (int nt = 0; nt < 4; nt++) {
            float* a4 = acc[mt][nt];
            const int row = m0 + wm * 64 + mt * 16 + er;
            const int col = n0 + wn * 32 + nt * 8 + ec;
            *(float2*)(Cp + (size_t)row * CD + col) =
                make_float2(a4[0] * kScale, a4[1] * kScale);
            *(float2*)(Cp + (size_t)(row + 8) * CD + col) =
                make_float2(a4[2] * kScale, a4[3] * kScale);
        }
    }
}

// ---------------------------------------------------------------------------
// GEMM2 (out): out[m][n] = sum_k attn[m][k]*x2[n][k], k = channel (768).
// K-contiguous, non-trans ldmatrix, ONE-TERM fp16 x fp16.
// CTA 128x128, 256 threads, BK=32, 3-stage. 2 CTAs/SM. (R11 config.)
// cp.async issue split into two half-bursts.
// ---------------------------------------------------------------------------
static constexpr int ROWB = 80;
static constexpr int TEN = 128 * ROWB;      // 10240
static constexpr int STG3 = 2 * TEN;        // 20480 (Ah, Bh)
static constexpr int SM2 = 3 * STG3;        // 61440

__global__ __launch_bounds__(256) void gemm2_kernel(float* __restrict__ Cout) {
    extern __shared__ char smc[];
    const uint32_t smb = smem_u32(smc);
    const int tid = threadIdx.x;
    const int wid = tid >> 5, lane = tid & 31;
    const int wm = wid >> 2, wn = wid & 3;
    const int b = blockIdx.z;
    const int m0 = blockIdx.y * 128;
    const int n0 = blockIdx.x * 128;

    const fp16* pAh = g_at_hi + (size_t)b * CD * CD + (size_t)m0 * CD;
    const fp16* pBh = g_x2n_hi + (size_t)b * ND * CD + (size_t)n0 * CD;
    float* Cp = Cout + (size_t)b * CD * ND;

    const int lrow = tid >> 2;
    const int lseg = tid & 3;

    auto issue_half = [&](int c, int buf, int h) {
        const int k0 = c * 32;
        const uint32_t sb = smb + buf * STG3;
        const int row = lrow + h * 64;
        const uint32_t so = (uint32_t)row * ROWB + lseg * 16;
        const size_t go = (size_t)row * CD + k0 + lseg * 8;
        cp_async16(sb + so, pAh + go);
        cp_async16(sb + TEN + so, pBh + go);
    };
    auto issue = [&](int c, int buf) {
        issue_half(c, buf, 0);
        issue_half(c, buf, 1);
        CP_COMMIT();
    };

    float acc[4][4][4] = {};
    constexpr int NC = CD / 32;  // 24

    issue(0, 0);
    issue(1, 1);

    const int a_r = lane & 15, a_h = lane >> 4;
    const int b_r = (lane & 7) + ((lane >> 4) << 3);
    const int b_h = (lane >> 3) & 1;

    int buf = 0;
    for (int c = 0; c < NC; c++) {
        const bool more = (c + 2 < NC);
        if (more) { CP_WAIT(1); } else { CP_WAIT(0); }
        __syncthreads();

        const uint32_t sA = smb + buf * STG3;
        const uint32_t sB = sA + TEN;
        int nb = buf + 2; if (nb >= 3) nb -= 3;

        uint32_t ah[4][4], bh[2][4];

        auto load_frags = [&](int ks) {
            const uint32_t kso = ks * 32;
#pragma unroll
            for (int mt = 0; mt < 4; mt++) {
                uint32_t addr = sA + (uint32_t)(wm * 64 + mt * 16 + a_r) * ROWB + kso + a_h * 16;
                ldsm4(ah[mt][0], ah[mt][1], ah[mt][2], ah[mt][3], addr);
            }
#pragma unroll
            for (int np = 0; np < 2; np++) {
                uint32_t addr = sB + (uint32_t)(wn * 32 + np * 16 + b_r) * ROWB + kso + b_h * 16;
                ldsm4(bh[np][0], bh[np][1], bh[np][2], bh[np][3], addr);
            }
        };
        auto mma_all = [&]() {
#pragma unroll
            for (int mt = 0; mt < 4; mt++)
#pragma unroll
                for (int nt = 0; nt < 4; nt++) {
                    const uint32_t* bph = &bh[nt >> 1][(nt & 1) * 2];
                    mma_f16(acc[mt][nt], ah[mt], bph);
                }
        };

        load_frags(0);
        if (more) issue_half(c + 2, nb, 0);
        mma_all();
        load_frags(1);
        if (more) { issue_half(c + 2, nb, 1); CP_COMMIT(); }
        mma_all();

        buf++; if (buf == 3) buf = 0;
    }

    const int er = lane >> 2, ec = (lane & 3) * 2;
#pragma unroll
    for (int mt = 0; mt < 4; mt++) {
#pragma unroll
        for (int nt = 0; nt < 4; nt++) {
            float* a4 = acc[mt][nt];
            const int row = m0 + wm * 64 + mt * 16 + er;
            const int col = n0 + wn * 32 + nt * 8 + ec;
            *(float2*)(Cp + (size_t)row * ND + col) = make_float2(a4[0], a4[1]);
            *(float2*)(Cp + (size_t)(row + 8) * ND + col) = make_float2(a4[2], a4[3]);
        }
    }
}

// ---------------------------------------------------------------------------
extern "C" void kernel_launch(void* const* d_in, const int* in_sizes, int n_in,
                              void* d_out, int out_size) {
    const float* x1 = (const float*)d_in[0];
    const float* x2 = (const float*)d_in[1];
    float* out = (float*)d_out;

    cudaFuncSetAttribute(gemm1_kernel,
                         cudaFuncAttributeMaxDynamicSharedMemorySize, SM1);
    cudaFuncSetAttribute(gemm2_kernel,
                         cudaFuncAttributeMaxDynamicSharedMemorySize, SM2);

    const int half = (int)((size_t)BB * ND * CD / 2048);  // 8 floats/thread
    split_kernel<<<2 * half, 256>>>(x1, x2);

    dim3 g1(CD / 128, CD / 128, BB);  // 6 x 6 x 8 = 288 CTAs (one wave)
    gemm1_kernel<<<g1, 256, SM1>>>();

    softmax_kernel<<<BB * CD, 256>>>();

    dim3 g2(ND / 128, CD / 128, BB);  // 32 x 6 x 8 = 768 CTAs
    gemm2_kernel<<<g2, 256, SM2>>>(out);
}

// round 17
// speedup vs baseline: 1.1282x; 1.0692x over previous
#include <cuda_runtime.h>
#include <cuda_fp16.h>
#include <cstdint>

#define CD 768
#define ND 4096
#define BB 8

using fp16 = __half;

// ---------------------------------------------------------------------------
// Device scratch (module-load allocated; no runtime allocs)
// ---------------------------------------------------------------------------
__device__ fp16 g_x1n_hi[(size_t)BB * ND * CD];  // x1 natural [b][n][c]
__device__ fp16 g_x1n_lo[(size_t)BB * ND * CD];
__device__ fp16 g_x2n_hi[(size_t)BB * ND * CD];  // x2 natural [b][n][c]
__device__ fp16 g_x2n_lo[(size_t)BB * ND * CD];
__device__ float g_attn[(size_t)BB * CD * CD];   // fp32 logits
__device__ fp16 g_at_hi[(size_t)BB * CD * CD];   // softmaxed attn (fp16)

__device__ __constant__ float kScale = 0.10206207261596577f;  // (768/8)^-0.5

// ---------------------------------------------------------------------------
// PTX helpers
// ---------------------------------------------------------------------------
__device__ __forceinline__ uint32_t smem_u32(const void* p) {
    uint32_t a;
    asm("{ .reg .u64 t; cvta.to.shared.u64 t, %1; cvt.u32.u64 %0, t; }" : "=r"(a) : "l"(p));
    return a;
}

__device__ __forceinline__ void cp_async16(uint32_t saddr, const void* gaddr) {
    asm volatile("cp.async.cg.shared.global [%0], [%1], 16;" :: "r"(saddr), "l"(gaddr));
}
#define CP_COMMIT() asm volatile("cp.async.commit_group;" ::: "memory")
#define CP_WAIT(n)  asm volatile("cp.async.wait_group %0;" :: "n"(n) : "memory")

__device__ __forceinline__ void ldsm4(uint32_t& r0, uint32_t& r1, uint32_t& r2,
                                      uint32_t& r3, uint32_t addr) {
    asm volatile("ldmatrix.sync.aligned.m8n8.x4.shared.b16 {%0,%1,%2,%3}, [%4];"
                 : "=r"(r0), "=r"(r1), "=r"(r2), "=r"(r3) : "r"(addr));
}
__device__ __forceinline__ void ldsm4t(uint32_t& r0, uint32_t& r1, uint32_t& r2,
                                       uint32_t& r3, uint32_t addr) {
    asm volatile("ldmatrix.sync.aligned.m8n8.x4.trans.shared.b16 {%0,%1,%2,%3}, [%4];"
                 : "=r"(r0), "=r"(r1), "=r"(r2), "=r"(r3) : "r"(addr));
}

__device__ __forceinline__ void mma_f16(float* c, const uint32_t* a, const uint32_t* b) {
    asm volatile(
        "mma.sync.aligned.m16n8k16.row.col.f32.f16.f16.f32 "
        "{%0,%1,%2,%3}, {%4,%5,%6,%7}, {%8,%9}, {%0,%1,%2,%3};"
        : "+f"(c[0]), "+f"(c[1]), "+f"(c[2]), "+f"(c[3])
        : "r"(a[0]), "r"(a[1]), "r"(a[2]), "r"(a[3]), "r"(b[0]), "r"(b[1]));
}

// ---------------------------------------------------------------------------
// Streaming fp16 split: 16 floats/thread, packed converts.
// ---------------------------------------------------------------------------
__global__ __launch_bounds__(256) void split_kernel(const float* __restrict__ x1,
                                                    const float* __restrict__ x2) {
    const int half = gridDim.x >> 1;
    const float* src;
    fp16 *dh, *dl;
    int blk = blockIdx.x;
    if (blk < half) {
        src = x1; dh = g_x1n_hi; dl = g_x1n_lo;
    } else {
        src = x2; dh = g_x2n_hi; dl = g_x2n_lo;
        blk -= half;
    }
    size_t base = ((size_t)blk * 256 + threadIdx.x) * 16;
#pragma unroll
    for (int g = 0; g < 2; g++) {
        size_t i = base + g * 8;
        float4 v0 = *(const float4*)(src + i);
        float4 v1 = *(const float4*)(src + i + 4);

        __half2 h[4], l[4];
        h[0] = __float22half2_rn(make_float2(v0.x, v0.y));
        h[1] = __float22half2_rn(make_float2(v0.z, v0.w));
        h[2] = __float22half2_rn(make_float2(v1.x, v1.y));
        h[3] = __float22half2_rn(make_float2(v1.z, v1.w));
        float2 r0 = __half22float2(h[0]);
        float2 r1 = __half22float2(h[1]);
        float2 r2 = __half22float2(h[2]);
        float2 r3 = __half22float2(h[3]);
        l[0] = __float22half2_rn(make_float2(v0.x - r0.x, v0.y - r0.y));
        l[1] = __float22half2_rn(make_float2(v0.z - r1.x, v0.w - r1.y));
        l[2] = __float22half2_rn(make_float2(v1.x - r2.x, v1.y - r2.y));
        l[3] = __float22half2_rn(make_float2(v1.z - r3.x, v1.w - r3.y));

        *(uint4*)(dh + i) = *(uint4*)h;
        *(uint4*)(dl + i) = *(uint4*)l;
    }
}

// ---------------------------------------------------------------------------
// Softmax over g_attn rows -> fp16 attn
// ---------------------------------------------------------------------------
__global__ __launch_bounds__(256) void softmax_kernel() {
    const size_t ro = (size_t)blockIdx.x * CD;
    float* p = g_attn + ro;
    const int tid = threadIdx.x;

    float v0 = p[tid], v1 = p[tid + 256], v2 = p[tid + 512];

    float m = fmaxf(fmaxf(v0, v1), v2);
#pragma unroll
    for (int o = 16; o > 0; o >>= 1) m = fmaxf(m, __shfl_xor_sync(0xffffffffu, m, o));

    __shared__ float sm[8], ss[8];
    if ((tid & 31) == 0) sm[tid >> 5] = m;
    __syncthreads();
    float bm = sm[0];
#pragma unroll
    for (int i = 1; i < 8; i++) bm = fmaxf(bm, sm[i]);

    float e0 = __expf(v0 - bm), e1 = __expf(v1 - bm), e2 = __expf(v2 - bm);
    float s = e0 + e1 + e2;
#pragma unroll
    for (int o = 16; o > 0; o >>= 1) s += __shfl_xor_sync(0xffffffffu, s, o);
    if ((tid & 31) == 0) ss[tid >> 5] = s;
    __syncthreads();
    float bs = 0.f;
#pragma unroll
    for (int i = 0; i < 8; i++) bs += ss[i];

    float inv = 1.0f / bs;
    g_at_hi[ro + tid]       = __float2half_rn(e0 * inv);
    g_at_hi[ro + tid + 256] = __float2half_rn(e1 * inv);
    g_at_hi[ro + tid + 512] = __float2half_rn(e2 * inv);
}

// ---------------------------------------------------------------------------
// GEMM1 (logits): attn[m][n] = scale * sum_k x1[k][m]*x2[k][n], k = seq dim.
// Natural [n][c] operands, ldmatrix.trans fragments, 3-term fp16 split.
// CTA 128x128, 256 threads, BK=32, 3-stage, one barrier per chunk.
// MMA terms hoisted OUTERMOST: consecutive MMAs target distinct accumulators
// (per-accumulator addition order unchanged -> bit-identical results).
// ---------------------------------------------------------------------------
static constexpr int ROW2 = 272;
static constexpr int TEN2 = 32 * ROW2;      // 8704
static constexpr int STG2 = 4 * TEN2;       // 34816
static constexpr int SM1 = 3 * STG2;        // 104448

__global__ __launch_bounds__(256) void gemm1_kernel() {
    extern __shared__ char smc[];
    const uint32_t smb = smem_u32(smc);
    const int tid = threadIdx.x;
    const int wid = tid >> 5, lane = tid & 31;
    const int wm = wid >> 2, wn = wid & 3;
    const int b = blockIdx.z;
    const int m0 = blockIdx.y * 128;
    const int n0 = blockIdx.x * 128;

    const fp16* pAh = g_x1n_hi + (size_t)b * ND * CD + m0;
    const fp16* pAl = g_x1n_lo + (size_t)b * ND * CD + m0;
    const fp16* pBh = g_x2n_hi + (size_t)b * ND * CD + n0;
    const fp16* pBl = g_x2n_lo + (size_t)b * ND * CD + n0;
    float* Cp = g_attn + (size_t)b * CD * CD;

    auto issue_half = [&](int c, int buf, int h) {
        const int k0 = c * 32;
        const uint32_t sb = smb + buf * STG2;
        const int idx = tid + h * 256;
        const int row = idx >> 4, seg = idx & 15;
        const uint32_t so = (uint32_t)row * ROW2 + seg * 16;
        const size_t go = (size_t)(k0 + row) * CD + seg * 8;
        cp_async16(sb + so, pAh + go);
        cp_async16(sb + TEN2 + so, pAl + go);
        cp_async16(sb + 2 * TEN2 + so, pBh + go);
        cp_async16(sb + 3 * TEN2 + so, pBl + go);
    };
    auto issue = [&](int c, int buf) {
        issue_half(c, buf, 0);
        issue_half(c, buf, 1);
        CP_COMMIT();
    };

    float acc[4][4][4] = {};
    constexpr int NC = ND / 32;  // 128

    issue(0, 0);
    issue(1, 1);

    const int a_kr = ((lane >> 4) << 3) + (lane & 7);
    const int a_mc = (lane >> 3) & 1;
    const int b_kr = (((lane >> 3) & 1) << 3) + (lane & 7);
    const int b_nc = lane >> 4;

    int buf = 0;
    for (int c = 0; c < NC; c++) {
        const bool more = (c + 2 < NC);
        if (more) { CP_WAIT(1); } else { CP_WAIT(0); }
        __syncthreads();

        const uint32_t sA = smb + buf * STG2;
        const uint32_t sB = sA + 2 * TEN2;
        int nb = buf + 2; if (nb >= 3) nb -= 3;

        uint32_t ah[4][4], al[4][4], bh[2][4], bl[2][4];

        auto load_frags = [&](int ks) {
            const uint32_t akro = (uint32_t)(ks * 16 + a_kr) * ROW2;
            const uint32_t bkro = (uint32_t)(ks * 16 + b_kr) * ROW2;
#pragma unroll
            for (int mt = 0; mt < 4; mt++) {
                uint32_t addr = sA + akro + (uint32_t)(wm * 128 + mt * 32 + a_mc * 16);
                ldsm4t(ah[mt][0], ah[mt][1], ah[mt][2], ah[mt][3], addr);
                ldsm4t(al[mt][0], al[mt][1], al[mt][2], al[mt][3], addr + TEN2);
            }
#pragma unroll
            for (int np = 0; np < 2; np++) {
                uint32_t addr = sB + bkro + (uint32_t)(wn * 64 + np * 32 + b_nc * 16);
                ldsm4t(bh[np][0], bh[np][1], bh[np][2], bh[np][3], addr);
                ldsm4t(bl[np][0], bl[np][1], bl[np][2], bl[np][3], addr + TEN2);
            }
        };
        // term loop OUTERMOST: 16 independent accumulators between reuses
        auto mma_all = [&]() {
#pragma unroll
            for (int t = 0; t < 3; t++)
#pragma unroll
                for (int mt = 0; mt < 4; mt++)
#pragma unroll
                    for (int nt = 0; nt < 4; nt++) {
                        const uint32_t* ap = (t == 2) ? al[mt] : ah[mt];
                        const uint32_t* bp = (t == 1) ? &bl[nt >> 1][(nt & 1) * 2]
                                                      : &bh[nt >> 1][(nt & 1) * 2];
                        mma_f16(acc[mt][nt], ap, bp);
                    }
        };

        load_frags(0);
        if (more) issue_half(c + 2, nb, 0);
        mma_all();
        load_frags(1);
        if (more) { issue_half(c + 2, nb, 1); CP_COMMIT(); }
        mma_all();

        buf++; if (buf == 3) buf = 0;
    }

    const int er = lane >> 2, ec = (lane & 3) * 2;
#pragma unroll
    for (int mt = 0; mt < 4; mt++) {
#pragma unroll
        for (int nt = 0; nt < 4; nt++) {
            float* a4 = acc[mt][nt];
            const int row = m0 + wm * 64 + mt * 16 + er;
            const int col = n0 + wn * 32 + nt * 8 + ec;
            *(float2*)(Cp + (size_t)row * CD + col) =
                make_float2(a4[0] * kScale, a4[1] * kScale);
            *(float2*)(Cp + (size_t)(row + 8) * CD + col) =
                make_float2(a4[2] * kScale, a4[3] * kScale);
        }
    }
}

// ---------------------------------------------------------------------------
// GEMM2 (out): out[m][n] = sum_k attn[m][k]*x2[n][k], k = channel (768).
// K-contiguous, non-trans ldmatrix, ONE-TERM fp16 x fp16.
// CTA 128x128, 256 threads, BK=32, FOUR-stage (prefetch distance 3).
// 80 KB smem -> 2 CTAs/SM.
// ---------------------------------------------------------------------------
static constexpr int ROWB = 80;
static constexpr int TEN = 128 * ROWB;      // 10240
static constexpr int STG3 = 2 * TEN;        // 20480 (Ah, Bh)
static constexpr int SM2 = 4 * STG3;        // 81920

__global__ __launch_bounds__(256) void gemm2_kernel(float* __restrict__ Cout) {
    extern __shared__ char smc[];
    const uint32_t smb = smem_u32(smc);
    const int tid = threadIdx.x;
    const int wid = tid >> 5, lane = tid & 31;
    const int wm = wid >> 2, wn = wid & 3;
    const int b = blockIdx.z;
    const int m0 = blockIdx.y * 128;
    const int n0 = blockIdx.x * 128;

    const fp16* pAh = g_at_hi + (size_t)b * CD * CD + (size_t)m0 * CD;
    const fp16* pBh = g_x2n_hi + (size_t)b * ND * CD + (size_t)n0 * CD;
    float* Cp = Cout + (size_t)b * CD * ND;

    const int lrow = tid >> 2;
    const int lseg = tid & 3;

    auto issue_half = [&](int c, int buf, int h) {
        const int k0 = c * 32;
        const uint32_t sb = smb + buf * STG3;
        const int row = lrow + h * 64;
        const uint32_t so = (uint32_t)row * ROWB + lseg * 16;
        const size_t go = (size_t)row * CD + k0 + lseg * 8;
        cp_async16(sb + so, pAh + go);
        cp_async16(sb + TEN + so, pBh + go);
    };
    auto issue = [&](int c, int buf) {
        issue_half(c, buf, 0);
        issue_half(c, buf, 1);
        CP_COMMIT();
    };

    float acc[4][4][4] = {};
    constexpr int NC = CD / 32;  // 24

    issue(0, 0);
    issue(1, 1);
    issue(2, 2);

    const int a_r = lane & 15, a_h = lane >> 4;
    const int b_r = (lane & 7) + ((lane >> 4) << 3);
    const int b_h = (lane >> 3) & 1;

    int buf = 0;
    for (int c = 0; c < NC; c++) {
        // chunk c must be complete: allowed pending = min(2, NC-1-c)
        if (c + 2 < NC) { CP_WAIT(2); }
        else if (c + 1 < NC) { CP_WAIT(1); }
        else { CP_WAIT(0); }
        __syncthreads();

        const uint32_t sA = smb + buf * STG3;
        const uint32_t sB = sA + TEN;
        const bool more = (c + 3 < NC);
        int nb = buf + 3; if (nb >= 4) nb -= 4;

        uint32_t ah[4][4], bh[2][4];

        auto load_frags = [&](int ks) {
            const uint32_t kso = ks * 32;
#pragma unroll
            for (int mt = 0; mt < 4; mt++) {
                uint32_t addr = sA + (uint32_t)(wm * 64 + mt * 16 + a_r) * ROWB + kso + a_h * 16;
                ldsm4(ah[mt][0], ah[mt][1], ah[mt][2], ah[mt][3], addr);
            }
#pragma unroll
            for (int np = 0; np < 2; np++) {
                uint32_t addr = sB + (uint32_t)(wn * 32 + np * 16 + b_r) * ROWB + kso + b_h * 16;
                ldsm4(bh[np][0], bh[np][1], bh[np][2], bh[np][3], addr);
            }
        };
        auto mma_all = [&]() {
#pragma unroll
            for (int mt = 0; mt < 4; mt++)
#pragma unroll
                for (int nt = 0; nt < 4; nt++) {
                    const uint32_t* bph = &bh[nt >> 1][(nt & 1) * 2];
                    mma_f16(acc[mt][nt], ah[mt], bph);
                }
        };

        load_frags(0);
        if (more) issue_half(c + 3, nb, 0);
        mma_all();
        load_frags(1);
        if (more) { issue_half(c + 3, nb, 1); CP_COMMIT(); }
        mma_all();

        buf++; if (buf == 4) buf = 0;
    }

    const int er = lane >> 2, ec = (lane & 3) * 2;
#pragma unroll
    for (int mt = 0; mt < 4; mt++) {
#pragma unroll
        for (int nt = 0; nt < 4; nt++) {
            float* a4 = acc[mt][nt];
            const int row = m0 + wm * 64 + mt * 16 + er;
            const int col = n0 + wn * 32 + nt * 8 + ec;
            *(float2*)(Cp + (size_t)row * ND + col) = make_float2(a4[0], a4[1]);
            *(float2*)(Cp + (size_t)(row + 8) * ND + col) = make_float2(a4[2], a4[3]);
        }
    }
}

// ---------------------------------------------------------------------------
extern "C" void kernel_launch(void* const* d_in, const int* in_sizes, int n_in,
                              void* d_out, int out_size) {
    const float* x1 = (const float*)d_in[0];
    const float* x2 = (const float*)d_in[1];
    float* out = (float*)d_out;

    cudaFuncSetAttribute(gemm1_kernel,
                         cudaFuncAttributeMaxDynamicSharedMemorySize, SM1);
    cudaFuncSetAttribute(gemm2_kernel,
                         cudaFuncAttributeMaxDynamicSharedMemorySize, SM2);

    const int half = (int)((size_t)BB * ND * CD / 4096);  // 16 floats/thread
    split_kernel<<<2 * half, 256>>>(x1, x2);

    dim3 g1(CD / 128, CD / 128, BB);  // 6 x 6 x 8 = 288 CTAs (one wave)
    gemm1_kernel<<<g1, 256, SM1>>>();

    softmax_kernel<<<BB * CD, 256>>>();

    dim3 g2(ND / 128, CD / 128, BB);  // 32 x 6 x 8 = 768 CTAs
    gemm2_kernel<<<g2, 256, SM2>>>(out);
}